// round 14
// baseline (speedup 1.0000x reference)
#include <cuda_runtime.h>
#include <math.h>
#include <stdint.h>

#define NSEQ 512
#define CHN  128
#define HD   128
#define NROWS (NSEQ*NSEQ)   // 262144

// Scratch (__device__ globals: allocation-free per harness rules)
__device__ float g_xn[(size_t)NROWS * CHN];   // LN(x) row-major [row][c]  (tf32-rounded)
__device__ float g_a [(size_t)HD * NROWS];    // channel-major [d][i*512+k] (tf32-rounded)
__device__ float g_b [(size_t)HD * NROWS];    // channel-major [d][j*512+k] (tf32-rounded)
__device__ float g_t [(size_t)HD * NROWS];    // channel-major [d][i*512+j] (fp32)
__device__ float g_tn[(size_t)NROWS * HD];    // LN_d(t) row-major [e][d]   (tf32-rounded)
__device__ float g_wr[98304];                 // tf32-rounded weights:
                                              // [0,32768) p_in, [32768,65536) g_in,
                                              // [65536,81920) p_out, [81920,98304) g_out

// ---------------------------------------------------------------------------
// helpers
// ---------------------------------------------------------------------------
__device__ __forceinline__ float tf32r(float f) {
    unsigned u;
    asm("cvt.rna.tf32.f32 %0, %1;" : "=r"(u) : "f"(f));
    return __uint_as_float(u);
}

__device__ __forceinline__ void mma_tf32(float* c, const unsigned* a, const unsigned* b) {
    asm volatile(
        "mma.sync.aligned.m16n8k8.row.col.f32.tf32.tf32.f32 "
        "{%0,%1,%2,%3}, {%4,%5,%6,%7}, {%8,%9}, {%0,%1,%2,%3};\n"
        : "+f"(c[0]), "+f"(c[1]), "+f"(c[2]), "+f"(c[3])
        : "r"(a[0]), "r"(a[1]), "r"(a[2]), "r"(a[3]), "r"(b[0]), "r"(b[1]));
}

__device__ __forceinline__ uint32_t smem_u32(const void* p) {
    uint32_t a;
    asm("{ .reg .u64 t; cvta.to.shared.u64 t, %1; cvt.u32.u64 %0, t; }"
        : "=r"(a) : "l"(p));
    return a;
}
__device__ __forceinline__ void cpasync16(uint32_t dst, const void* src) {
    asm volatile("cp.async.cg.shared.global [%0], [%1], 16;" :: "r"(dst), "l"(src));
}
#define CP_COMMIT() asm volatile("cp.async.commit_group;" ::: "memory")
#define CP_WAIT0()  asm volatile("cp.async.wait_group 0;" ::: "memory")
#define CP_WAIT1()  asm volatile("cp.async.wait_group 1;" ::: "memory")

// ldmatrix x4: four 8x8 b16 tiles; for tf32 data each lane receives one 4-byte
// element per tile with mapping (row = lane>>2, tf32col = lane&3).
__device__ __forceinline__ void ldsm4(unsigned& r0, unsigned& r1,
                                      unsigned& r2, unsigned& r3, uint32_t addr) {
    asm volatile("ldmatrix.sync.aligned.m8n8.x4.shared.b16 {%0,%1,%2,%3}, [%4];"
                 : "=r"(r0), "=r"(r1), "=r"(r2), "=r"(r3) : "r"(addr));
}

// ---------------------------------------------------------------------------
// KP: tf32-round all weight matrices once into g_wr.
// ---------------------------------------------------------------------------
__global__ void kprep(const float* __restrict__ pw, const float* __restrict__ gw,
                      const float* __restrict__ po, const float* __restrict__ go) {
    int i = blockIdx.x * 256 + threadIdx.x;        // grid covers 98304
    if (i < 32768)        g_wr[i] = tf32r(pw[i]);
    else if (i < 65536)   g_wr[i] = tf32r(gw[i - 32768]);
    else if (i < 81920)   g_wr[i] = tf32r(po[i - 65536]);
    else                  g_wr[i] = tf32r(go[i - 81920]);
}

// ---------------------------------------------------------------------------
// K0: xn = LayerNorm(x) over C=128.  One warp per row; output tf32-rounded.
// ---------------------------------------------------------------------------
__global__ void k0_ln(const float* __restrict__ x,
                      const float* __restrict__ w,
                      const float* __restrict__ b) {
    int row  = blockIdx.x * blockDim.y + threadIdx.y;
    int lane = threadIdx.x;
    const float* xr = x + (size_t)row * CHN;
    float4 v = *(const float4*)(xr + lane * 4);
    float s = v.x + v.y + v.z + v.w;
    float q = v.x*v.x + v.y*v.y + v.z*v.z + v.w*v.w;
    #pragma unroll
    for (int o = 16; o > 0; o >>= 1) {
        s += __shfl_xor_sync(0xffffffffu, s, o);
        q += __shfl_xor_sync(0xffffffffu, q, o);
    }
    float mean = s * (1.0f / CHN);
    float var  = q * (1.0f / CHN) - mean * mean;
    float rstd = rsqrtf(var + 1e-5f);
    float4 wv = *(const float4*)(w + lane * 4);
    float4 bv = *(const float4*)(b + lane * 4);
    float4 o;
    o.x = tf32r((v.x - mean) * rstd * wv.x + bv.x);
    o.y = tf32r((v.y - mean) * rstd * wv.y + bv.y);
    o.z = tf32r((v.z - mean) * rstd * wv.z + bv.z);
    o.w = tf32r((v.w - mean) * rstd * wv.w + bv.w);
    *(float4*)(g_xn + (size_t)row * CHN + lane * 4) = o;
}

// ---------------------------------------------------------------------------
// K1 (tf32 MMA + cp.async 3-stage + ldmatrix): h = (xn@p^T)*sigmoid(xn@g^T)
// ---------------------------------------------------------------------------
#define K1S 36
#define K1_ABUF (128 * K1S)
#define K1_WBUF (64 * K1S)
#define K1_STAGE (K1_ABUF + 2 * K1_WBUF)
#define K1_SMEM_BYTES (3 * K1_STAGE * 4)    // 110592

__global__ void __launch_bounds__(256)
k1_proj() {
    extern __shared__ float sm1[];
    int tid = threadIdx.x;
    int rowTile = blockIdx.x * 128;
    int chTile  = blockIdx.y * 64;
    const float* wp = g_wr;
    const float* wg = g_wr + 32768;
    int w = tid >> 5, lane = tid & 31;
    int wi = w & 3, wj = w >> 2;
    int gid = lane >> 2, tig = lane & 3;

    int rL = lane & 7;
    int aOff = (rL + ((lane >> 3) & 1) * 8) * (K1S * 4) + (lane >> 4) * 16;
    int bOff = (rL + (lane >> 4) * 8) * (K1S * 4) + ((lane >> 3) & 1) * 16;

    float accP[2][4][4] = {}, accG[2][4][4] = {};

    auto load_stage = [&](int s, int buf) {
        int k0 = s * 32;
        float* As = sm1 + buf * K1_STAGE;
        float* Ps = As + K1_ABUF;
        float* Gs = Ps + K1_WBUF;
        #pragma unroll
        for (int rep = 0; rep < 4; rep++) {
            int f = tid + rep * 256;          // 0..1023
            int k4 = f & 7, r = f >> 3;
            cpasync16(smem_u32(As + r * K1S + k4 * 4),
                      g_xn + (size_t)(rowTile + r) * CHN + k0 + k4 * 4);
        }
        #pragma unroll
        for (int rep = 0; rep < 2; rep++) {
            int f = tid + rep * 256;          // 0..511
            int k4 = f & 7, c = f >> 3;
            cpasync16(smem_u32(Ps + c * K1S + k4 * 4),
                      wp + (size_t)(chTile + c) * CHN + k0 + k4 * 4);
            cpasync16(smem_u32(Gs + c * K1S + k4 * 4),
                      wg + (size_t)(chTile + c) * CHN + k0 + k4 * 4);
        }
    };

    load_stage(0, 0);
    CP_COMMIT();
    load_stage(1, 1);
    CP_COMMIT();

    for (int s = 0; s < 4; s++) {
        int cur = s % 3;
        if (s + 1 < 4) CP_WAIT1(); else CP_WAIT0();   // group s complete
        __syncthreads();
        if (s + 2 < 4) {
            load_stage(s + 2, (s + 2) % 3);   // overwrites buf (s-1)%3; its
            CP_COMMIT();                      // readers finished before sync
        }

        float* As = sm1 + cur * K1_STAGE;
        float* Ps = As + K1_ABUF;
        float* Gs = Ps + K1_WBUF;
        uint32_t aB = smem_u32(As) + aOff + (wi * 32) * (K1S * 4);
        uint32_t pB = smem_u32(Ps) + bOff + (wj * 32) * (K1S * 4);
        uint32_t gB = smem_u32(Gs) + bOff + (wj * 32) * (K1S * 4);

        #pragma unroll
        for (int kk = 0; kk < 4; kk++) {
            int kbB = kk * 32;   // bytes
            unsigned a[2][4];
            #pragma unroll
            for (int mi = 0; mi < 2; mi++)
                ldsm4(a[mi][0], a[mi][1], a[mi][2], a[mi][3],
                      aB + mi * 16 * (K1S * 4) + kbB);
            #pragma unroll
            for (int nj2 = 0; nj2 < 2; nj2++) {
                unsigned pb[4], gb[4];
                ldsm4(pb[0], pb[1], pb[2], pb[3],
                      pB + nj2 * 16 * (K1S * 4) + kbB);
                ldsm4(gb[0], gb[1], gb[2], gb[3],
                      gB + nj2 * 16 * (K1S * 4) + kbB);
                #pragma unroll
                for (int mi = 0; mi < 2; mi++) {
                    mma_tf32(accP[mi][nj2 * 2 + 0], a[mi], pb + 0);
                    mma_tf32(accG[mi][nj2 * 2 + 0], a[mi], gb + 0);
                    mma_tf32(accP[mi][nj2 * 2 + 1], a[mi], pb + 2);
                    mma_tf32(accG[mi][nj2 * 2 + 1], a[mi], gb + 2);
                }
            }
        }
    }
    __syncthreads();   // all warps done with final stage before Hs overwrite

    // epilogue: h = P * sigmoid(G); per-warp smem transpose -> channel-major
    float* Hs = sm1 + w * (32 * 33);
    #pragma unroll
    for (int mi = 0; mi < 2; mi++)
        #pragma unroll
        for (int nj = 0; nj < 4; nj++)
            #pragma unroll
            for (int c = 0; c < 4; c++) {
                float h = accP[mi][nj][c] / (1.0f + __expf(-accG[mi][nj][c]));
                int row = mi * 16 + gid + ((c >> 1) << 3);
                int ch  = nj * 8 + tig * 2 + (c & 1);
                Hs[ch * 33 + row] = tf32r(h);
            }
    __syncwarp();
    {
        int chG = chTile + wj * 32 + lane;
        float* dst = (chG < HD) ? (g_a + (size_t)chG * NROWS)
                                : (g_b + (size_t)(chG - HD) * NROWS);
        size_t base = (size_t)rowTile + wi * 32;
        #pragma unroll
        for (int r4 = 0; r4 < 8; r4++) {
            float4 o;
            o.x = Hs[lane * 33 + r4 * 4 + 0];
            o.y = Hs[lane * 33 + r4 * 4 + 1];
            o.z = Hs[lane * 33 + r4 * 4 + 2];
            o.w = Hs[lane * 33 + r4 * 4 + 3];
            *(float4*)(dst + base + r4 * 4) = o;
        }
    }
}

// ---------------------------------------------------------------------------
// K2 (tf32 MMA + cp.async 3-stage + ldmatrix): 256 thr, warp tile 32x64.
// Same accumulation order as before -> bit-identical result.
// ---------------------------------------------------------------------------
#define K2S 36
#define K2_BUF (128 * K2S)
#define K2_STAGE (2 * K2_BUF)               // A + B per stage
#define K2_SMEM_BYTES (3 * K2_STAGE * 4)    // 110592

__global__ void __launch_bounds__(256)
k2_einsum() {
    extern __shared__ float sm2[];
    int tid = threadIdx.x;
    int d = blockIdx.z;
    int iTile = blockIdx.x * 128;
    int jTile = blockIdx.y * 128;
    const float* Ab = g_a + (size_t)d * NROWS;
    const float* Bb = g_b + (size_t)d * NROWS;
    int w = tid >> 5, lane = tid & 31;
    int wi = w & 3, wj = w >> 2;
    int gid = lane >> 2, tig = lane & 3;

    int rL = lane & 7;
    int aOff = (rL + ((lane >> 3) & 1) * 8) * (K2S * 4) + (lane >> 4) * 16;
    int bOff = (rL + (lane >> 4) * 8) * (K2S * 4) + ((lane >> 3) & 1) * 16;

    float acc[2][8][4] = {};

    auto load_stage = [&](int s, int buf) {
        int k0 = s * 32;
        float* Ad = sm2 + buf * K2_STAGE;
        float* Bd = Ad + K2_BUF;
        #pragma unroll
        for (int rep = 0; rep < 4; rep++) {
            int f = tid + rep * 256;
            int k4 = f & 7, r = f >> 3;
            cpasync16(smem_u32(Ad + r * K2S + k4 * 4),
                      Ab + (size_t)(iTile + r) * NSEQ + k0 + k4 * 4);
            cpasync16(smem_u32(Bd + r * K2S + k4 * 4),
                      Bb + (size_t)(jTile + r) * NSEQ + k0 + k4 * 4);
        }
    };

    load_stage(0, 0);
    CP_COMMIT();
    load_stage(1, 1);
    CP_COMMIT();

    for (int s = 0; s < 16; s++) {
        int cur = s % 3;
        if (s + 1 < 16) CP_WAIT1(); else CP_WAIT0();
        __syncthreads();
        if (s + 2 < 16) {
            load_stage(s + 2, (s + 2) % 3);
            CP_COMMIT();
        }

        float* As = sm2 + cur * K2_STAGE;
        float* Bs = As + K2_BUF;
        uint32_t aB = smem_u32(As) + aOff + (wi * 32) * (K2S * 4);
        uint32_t bB = smem_u32(Bs) + bOff + (wj * 64) * (K2S * 4);

        #pragma unroll
        for (int kk = 0; kk < 4; kk++) {
            int kbB = kk * 32;
            unsigned a[2][4];
            #pragma unroll
            for (int mi = 0; mi < 2; mi++)
                ldsm4(a[mi][0], a[mi][1], a[mi][2], a[mi][3],
                      aB + mi * 16 * (K2S * 4) + kbB);
            #pragma unroll
            for (int nj2 = 0; nj2 < 4; nj2++) {
                unsigned bb[4];
                ldsm4(bb[0], bb[1], bb[2], bb[3],
                      bB + nj2 * 16 * (K2S * 4) + kbB);
                #pragma unroll
                for (int mi = 0; mi < 2; mi++) {
                    mma_tf32(acc[mi][nj2 * 2 + 0], a[mi], bb + 0);
                    mma_tf32(acc[mi][nj2 * 2 + 1], a[mi], bb + 2);
                }
            }
        }
    }

    float* T = g_t + (size_t)d * NROWS;
    #pragma unroll
    for (int mi = 0; mi < 2; mi++)
        #pragma unroll
        for (int nj = 0; nj < 8; nj++) {
            int r0 = iTile + wi * 32 + mi * 16 + gid;
            int cj = jTile + wj * 64 + nj * 8 + tig * 2;
            float2 v0 = make_float2(acc[mi][nj][0], acc[mi][nj][1]);
            *(float2*)(T + (size_t)r0 * NSEQ + cj) = v0;
            float2 v1 = make_float2(acc[mi][nj][2], acc[mi][nj][3]);
            *(float2*)(T + (size_t)(r0 + 8) * NSEQ + cj) = v1;
        }
}

// ---------------------------------------------------------------------------
// K3a: tn = LayerNorm_d(t): unchanged (at memory floor).
// ---------------------------------------------------------------------------
__global__ void __launch_bounds__(256)
k3a_ln(const float* __restrict__ nw, const float* __restrict__ nb) {
    __shared__ float Ts[64][132];
    __shared__ float red[4][64], red2[4][64];
    __shared__ float mS[64], rS[64];
    int tid = threadIdx.x;
    int e0 = blockIdx.x * 64;

    #pragma unroll
    for (int rep = 0; rep < 32; rep++) {
        int f = tid + rep * 256;
        int e = f & 63;
        int d = f >> 6;
        Ts[e][d] = g_t[(size_t)d * NROWS + e0 + e];
    }
    __syncthreads();

    {
        int e = tid & 63;
        int dc = tid >> 6;
        float s = 0.f, q = 0.f;
        #pragma unroll
        for (int u4 = 0; u4 < 8; u4++) {
            float4 v = *(const float4*)&Ts[e][dc * 32 + u4 * 4];
            s += v.x + v.y + v.z + v.w;
            q += v.x*v.x + v.y*v.y + v.z*v.z + v.w*v.w;
        }
        red[dc][e] = s;
        red2[dc][e] = q;
    }
    __syncthreads();
    if (tid < 64) {
        float s = red[0][tid] + red[1][tid] + red[2][tid] + red[3][tid];
        float q = red2[0][tid] + red2[1][tid] + red2[2][tid] + red2[3][tid];
        float mean = s * (1.0f / HD);
        float var  = q * (1.0f / HD) - mean * mean;
        mS[tid] = mean;
        rS[tid] = rsqrtf(var + 1e-5f);
    }
    __syncthreads();

    {
        int d4 = tid & 31;
        float4 wv = *(const float4*)(nw + d4 * 4);
        float4 bv = *(const float4*)(nb + d4 * 4);
        #pragma unroll
        for (int rep = 0; rep < 8; rep++) {
            int e = (tid >> 5) + rep * 8;
            float mean = mS[e], rstd = rS[e];
            float4 v = *(const float4*)&Ts[e][d4 * 4];
            float4 o;
            o.x = tf32r((v.x - mean) * rstd * wv.x + bv.x);
            o.y = tf32r((v.y - mean) * rstd * wv.y + bv.y);
            o.z = tf32r((v.z - mean) * rstd * wv.z + bv.z);
            o.w = tf32r((v.w - mean) * rstd * wv.w + bv.w);
            *(float4*)(g_tn + (size_t)(e0 + e) * HD + d4 * 4) = o;
        }
    }
}

// ---------------------------------------------------------------------------
// K3b (tf32 MMA + cp.async 3-stage + ldmatrix): out = (tn@p_out^T)*sigmoid(xn@g_out^T)
// ---------------------------------------------------------------------------
#define K3S 20
#define K3_ABUF (128 * K3S)
#define K3_WBUF (64 * K3S)
#define K3_STAGE (2 * K3_ABUF + 2 * K3_WBUF)
#define K3_SMEM_BYTES (3 * K3_STAGE * 4)    // 92160

__global__ void __launch_bounds__(256)
k3b_out(float* __restrict__ out) {
    extern __shared__ float sm3[];
    int tid = threadIdx.x;
    int rowTile = blockIdx.x * 128;
    int chTile  = blockIdx.y * 64;
    const float* powt = g_wr + 65536;
    const float* gowt = g_wr + 81920;
    int w = tid >> 5, lane = tid & 31;
    int wi = w & 3, wj = w >> 2;
    int gid = lane >> 2, tig = lane & 3;

    int rL = lane & 7;
    int aOff = (rL + ((lane >> 3) & 1) * 8) * (K3S * 4) + (lane >> 4) * 16;
    int bOff = (rL + (lane >> 4) * 8) * (K3S * 4) + ((lane >> 3) & 1) * 16;

    float accO[2][4][4] = {}, accG[2][4][4] = {};

    auto load_stage = [&](int s, int buf) {
        int k0 = s * 16;
        float* As = sm3 + buf * K3_STAGE;
        float* Xs = As + K3_ABUF;
        float* Ps = Xs + K3_ABUF;
        float* Gs = Ps + K3_WBUF;
        #pragma unroll
        for (int rep = 0; rep < 2; rep++) {
            int f = tid + rep * 256;          // 0..511
            int k4 = f & 3, r = f >> 2;       // r 0..127
            cpasync16(smem_u32(As + r * K3S + k4 * 4),
                      g_tn + (size_t)(rowTile + r) * HD + k0 + k4 * 4);
            cpasync16(smem_u32(Xs + r * K3S + k4 * 4),
                      g_xn + (size_t)(rowTile + r) * CHN + k0 + k4 * 4);
        }
        {
            int f = tid;                      // 0..255
            int k4 = f & 3, c = f >> 2;       // c 0..63
            cpasync16(smem_u32(Ps + c * K3S + k4 * 4),
                      powt + (size_t)(chTile + c) * HD + k0 + k4 * 4);
            cpasync16(smem_u32(Gs + c * K3S + k4 * 4),
                      gowt + (size_t)(chTile + c) * CHN + k0 + k4 * 4);
        }
    };

    load_stage(0, 0);
    CP_COMMIT();
    load_stage(1, 1);
    CP_COMMIT();

    for (int s = 0; s < 8; s++) {
        int cur = s % 3;
        if (s + 1 < 8) CP_WAIT1(); else CP_WAIT0();
        __syncthreads();
        if (s + 2 < 8) {
            load_stage(s + 2, (s + 2) % 3);
            CP_COMMIT();
        }

        float* As = sm3 + cur * K3_STAGE;
        float* Xs = As + K3_ABUF;
        float* Ps = Xs + K3_ABUF;
        float* Gs = Ps + K3_WBUF;
        uint32_t aB = smem_u32(As) + aOff + (wi * 32) * (K3S * 4);
        uint32_t xB = smem_u32(Xs) + aOff + (wi * 32) * (K3S * 4);
        uint32_t pB = smem_u32(Ps) + bOff + (wj * 32) * (K3S * 4);
        uint32_t gB = smem_u32(Gs) + bOff + (wj * 32) * (K3S * 4);

        #pragma unroll
        for (int kk = 0; kk < 2; kk++) {
            int kbB = kk * 32;
            unsigned a[2][4], x[2][4];
            #pragma unroll
            for (int mi = 0; mi < 2; mi++) {
                ldsm4(a[mi][0], a[mi][1], a[mi][2], a[mi][3],
                      aB + mi * 16 * (K3S * 4) + kbB);
                ldsm4(x[mi][0], x[mi][1], x[mi][2], x[mi][3],
                      xB + mi * 16 * (K3S * 4) + kbB);
            }
            #pragma unroll
            for (int nj2 = 0; nj2 < 2; nj2++) {
                unsigned pb[4], gb[4];
                ldsm4(pb[0], pb[1], pb[2], pb[3],
                      pB + nj2 * 16 * (K3S * 4) + kbB);
                ldsm4(gb[0], gb[1], gb[2], gb[3],
                      gB + nj2 * 16 * (K3S * 4) + kbB);
                #pragma unroll
                for (int mi = 0; mi < 2; mi++) {
                    mma_tf32(accO[mi][nj2 * 2 + 0], a[mi], pb + 0);
                    mma_tf32(accG[mi][nj2 * 2 + 0], x[mi], gb + 0);
                    mma_tf32(accO[mi][nj2 * 2 + 1], a[mi], pb + 2);
                    mma_tf32(accG[mi][nj2 * 2 + 1], x[mi], gb + 2);
                }
            }
        }
    }

    #pragma unroll
    for (int mi = 0; mi < 2; mi++)
        #pragma unroll
        for (int nj = 0; nj < 4; nj++) {
            int r0 = rowTile + wi * 32 + mi * 16 + gid;
            int cj = chTile + wj * 32 + nj * 8 + tig * 2;
            float2 v0;
            v0.x = accO[mi][nj][0] / (1.0f + __expf(-accG[mi][nj][0]));
            v0.y = accO[mi][nj][1] / (1.0f + __expf(-accG[mi][nj][1]));
            *(float2*)(out + (size_t)r0 * CHN + cj) = v0;
            float2 v1;
            v1.x = accO[mi][nj][2] / (1.0f + __expf(-accG[mi][nj][2]));
            v1.y = accO[mi][nj][3] / (1.0f + __expf(-accG[mi][nj][3]));
            *(float2*)(out + (size_t)(r0 + 8) * CHN + cj) = v1;
        }
}

// ---------------------------------------------------------------------------
extern "C" void kernel_launch(void* const* d_in, const int* in_sizes, int n_in,
                              void* d_out, int out_size) {
    const float* x       = (const float*)d_in[0];
    const float* nin_w   = (const float*)d_in[1];
    const float* nin_b   = (const float*)d_in[2];
    const float* p_in_w  = (const float*)d_in[3];
    const float* g_in_w  = (const float*)d_in[4];
    const float* nout_w  = (const float*)d_in[5];
    const float* nout_b  = (const float*)d_in[6];
    const float* p_out_w = (const float*)d_in[7];
    const float* g_out_w = (const float*)d_in[8];
    float* out = (float*)d_out;

    cudaFuncSetAttribute(k1_proj,
                         cudaFuncAttributeMaxDynamicSharedMemorySize, K1_SMEM_BYTES);
    cudaFuncSetAttribute(k2_einsum,
                         cudaFuncAttributeMaxDynamicSharedMemorySize, K2_SMEM_BYTES);
    cudaFuncSetAttribute(k3b_out,
                         cudaFuncAttributeMaxDynamicSharedMemorySize, K3_SMEM_BYTES);

    kprep    <<<384, 256>>>(p_in_w, g_in_w, p_out_w, g_out_w);
    k0_ln    <<<NROWS / 8, dim3(32, 8)>>>(x, nin_w, nin_b);
    k1_proj  <<<dim3(NROWS / 128, 4), 256, K1_SMEM_BYTES>>>();
    k2_einsum<<<dim3(4, 4, 128), 256, K2_SMEM_BYTES>>>();
    k3a_ln   <<<NROWS / 64, 256>>>(nout_w, nout_b);
    k3b_out  <<<dim3(NROWS / 128, 2), 256, K3_SMEM_BYTES>>>(out);
}

// round 16
// speedup vs baseline: 1.0308x; 1.0308x over previous
#include <cuda_runtime.h>
#include <math.h>
#include <stdint.h>

#define NSEQ 512
#define CHN  128
#define HD   128
#define NROWS (NSEQ*NSEQ)   // 262144

// Scratch (__device__ globals: allocation-free per harness rules)
__device__ float g_xn[(size_t)NROWS * CHN];   // LN(x) row-major [row][c]  (tf32-rounded)
__device__ float g_a [(size_t)HD * NROWS];    // channel-major [d][i*512+k] (tf32-rounded)
__device__ float g_b [(size_t)HD * NROWS];    // channel-major [d][j*512+k] (tf32-rounded)
__device__ float g_t [(size_t)HD * NROWS];    // channel-major [d][i*512+j] (fp32)
__device__ float g_tn[(size_t)NROWS * HD];    // LN_d(t) row-major [e][d]   (tf32-rounded)
__device__ float g_wr[98304];                 // tf32-rounded weights:
                                              // [0,32768) p_in, [32768,65536) g_in,
                                              // [65536,81920) p_out, [81920,98304) g_out

// ---------------------------------------------------------------------------
// helpers
// ---------------------------------------------------------------------------
__device__ __forceinline__ float tf32r(float f) {
    unsigned u;
    asm("cvt.rna.tf32.f32 %0, %1;" : "=r"(u) : "f"(f));
    return __uint_as_float(u);
}

__device__ __forceinline__ void mma_tf32(float* c, const unsigned* a, const unsigned* b) {
    asm volatile(
        "mma.sync.aligned.m16n8k8.row.col.f32.tf32.tf32.f32 "
        "{%0,%1,%2,%3}, {%4,%5,%6,%7}, {%8,%9}, {%0,%1,%2,%3};\n"
        : "+f"(c[0]), "+f"(c[1]), "+f"(c[2]), "+f"(c[3])
        : "r"(a[0]), "r"(a[1]), "r"(a[2]), "r"(a[3]), "r"(b[0]), "r"(b[1]));
}

__device__ __forceinline__ uint32_t smem_u32(const void* p) {
    uint32_t a;
    asm("{ .reg .u64 t; cvta.to.shared.u64 t, %1; cvt.u32.u64 %0, t; }"
        : "=r"(a) : "l"(p));
    return a;
}
__device__ __forceinline__ void cpasync16(uint32_t dst, const void* src) {
    asm volatile("cp.async.cg.shared.global [%0], [%1], 16;" :: "r"(dst), "l"(src));
}
#define CP_COMMIT() asm volatile("cp.async.commit_group;" ::: "memory")
#define CP_WAIT0()  asm volatile("cp.async.wait_group 0;" ::: "memory")
#define CP_WAIT1()  asm volatile("cp.async.wait_group 1;" ::: "memory")

// ldmatrix x4: four 8x8 b16 tiles; for tf32 data each lane receives one 4-byte
// element per tile with mapping (row = lane>>2, tf32col = lane&3).
__device__ __forceinline__ void ldsm4(unsigned& r0, unsigned& r1,
                                      unsigned& r2, unsigned& r3, uint32_t addr) {
    asm volatile("ldmatrix.sync.aligned.m8n8.x4.shared.b16 {%0,%1,%2,%3}, [%4];"
                 : "=r"(r0), "=r"(r1), "=r"(r2), "=r"(r3) : "r"(addr));
}

// ---------------------------------------------------------------------------
// KP: tf32-round all weight matrices once into g_wr.
// ---------------------------------------------------------------------------
__global__ void kprep(const float* __restrict__ pw, const float* __restrict__ gw,
                      const float* __restrict__ po, const float* __restrict__ go) {
    int i = blockIdx.x * 256 + threadIdx.x;        // grid covers 98304
    if (i < 32768)        g_wr[i] = tf32r(pw[i]);
    else if (i < 65536)   g_wr[i] = tf32r(gw[i - 32768]);
    else if (i < 81920)   g_wr[i] = tf32r(po[i - 65536]);
    else                  g_wr[i] = tf32r(go[i - 81920]);
}

// ---------------------------------------------------------------------------
// K0: xn = LayerNorm(x) over C=128.  One warp per row; output tf32-rounded.
// ---------------------------------------------------------------------------
__global__ void k0_ln(const float* __restrict__ x,
                      const float* __restrict__ w,
                      const float* __restrict__ b) {
    int row  = blockIdx.x * blockDim.y + threadIdx.y;
    int lane = threadIdx.x;
    const float* xr = x + (size_t)row * CHN;
    float4 v = *(const float4*)(xr + lane * 4);
    float s = v.x + v.y + v.z + v.w;
    float q = v.x*v.x + v.y*v.y + v.z*v.z + v.w*v.w;
    #pragma unroll
    for (int o = 16; o > 0; o >>= 1) {
        s += __shfl_xor_sync(0xffffffffu, s, o);
        q += __shfl_xor_sync(0xffffffffu, q, o);
    }
    float mean = s * (1.0f / CHN);
    float var  = q * (1.0f / CHN) - mean * mean;
    float rstd = rsqrtf(var + 1e-5f);
    float4 wv = *(const float4*)(w + lane * 4);
    float4 bv = *(const float4*)(b + lane * 4);
    float4 o;
    o.x = tf32r((v.x - mean) * rstd * wv.x + bv.x);
    o.y = tf32r((v.y - mean) * rstd * wv.y + bv.y);
    o.z = tf32r((v.z - mean) * rstd * wv.z + bv.z);
    o.w = tf32r((v.w - mean) * rstd * wv.w + bv.w);
    *(float4*)(g_xn + (size_t)row * CHN + lane * 4) = o;
}

// ---------------------------------------------------------------------------
// K1 (tf32 MMA + cp.async + ldmatrix, WEIGHT-RESIDENT): per CTA, load P/G for
// its chTile ONCE (full K=128, [c][132]), then loop 4 rowTiles streaming only
// the A tiles (2-stage). Accumulation order per output unchanged vs R13.
// ---------------------------------------------------------------------------
#define K1S 36
#define K1_ABUF (128 * K1S)                 // 4608 floats per A stage
#define K1_WST 132
#define K1_WSZ (64 * K1_WST)                // 8448 floats per weight matrix
#define K1_W_OFF (2 * K1_ABUF)              // 9216
#define K1_SMEM_BYTES ((2 * K1_ABUF + 2 * K1_WSZ) * 4)   // 104448

__global__ void __launch_bounds__(256)
k1_proj() {
    extern __shared__ float sm1[];
    int tid = threadIdx.x;
    int rowGrp = blockIdx.x;                // 0..511, 4 rowTiles each
    int chTile = blockIdx.y * 64;
    const float* wp = g_wr;
    const float* wg = g_wr + 32768;
    int w = tid >> 5, lane = tid & 31;
    int wi = w & 3, wj = w >> 2;
    int gid = lane >> 2, tig = lane & 3;

    int rL = lane & 7;
    int aOff  = (rL + ((lane >> 3) & 1) * 8) * (K1S * 4) + (lane >> 4) * 16;
    int bOffW = (rL + (lane >> 4) * 8) * (K1_WST * 4) + ((lane >> 3) & 1) * 16;

    float* Ps = sm1 + K1_W_OFF;
    float* Gs = Ps + K1_WSZ;

    // Load weights once: 64 c x 128 k per matrix (2048 float4 each)
    #pragma unroll
    for (int rep = 0; rep < 8; rep++) {
        int f = tid + rep * 256;            // 0..2047
        int k4 = f & 31, c = f >> 5;        // k4 0..31, c 0..63
        cpasync16(smem_u32(Ps + c * K1_WST + k4 * 4),
                  wp + (size_t)(chTile + c) * CHN + k4 * 4);
        cpasync16(smem_u32(Gs + c * K1_WST + k4 * 4),
                  wg + (size_t)(chTile + c) * CHN + k4 * 4);
    }

    uint32_t pB = smem_u32(Ps) + bOffW + (wj * 32) * (K1_WST * 4);
    uint32_t gB = smem_u32(Gs) + bOffW + (wj * 32) * (K1_WST * 4);

    auto load_stage = [&](int rowTile, int s, int buf) {
        int k0 = s * 32;
        float* As = sm1 + buf * K1_ABUF;
        #pragma unroll
        for (int rep = 0; rep < 4; rep++) {
            int f = tid + rep * 256;        // 0..1023
            int k4 = f & 7, r = f >> 3;
            cpasync16(smem_u32(As + r * K1S + k4 * 4),
                      g_xn + (size_t)(rowTile + r) * CHN + k0 + k4 * 4);
        }
    };

    for (int rt = 0; rt < 4; rt++) {
        int rowTile = (rowGrp * 4 + rt) * 128;
        float accP[2][4][4] = {}, accG[2][4][4] = {};

        load_stage(rowTile, 0, 0);
        CP_COMMIT();                        // rt==0: this group also carries weights

        for (int s = 0; s < 4; s++) {
            int cur = s & 1;
            if (s + 1 < 4) {
                load_stage(rowTile, s + 1, 1 - cur);
                CP_COMMIT();
                CP_WAIT1();                 // stage s (and weights, first time)
            } else {
                CP_WAIT0();
            }
            __syncthreads();

            float* As = sm1 + cur * K1_ABUF;
            uint32_t aB = smem_u32(As) + aOff + (wi * 32) * (K1S * 4);
            int ksB = s * 128;              // 32 tf32 * 4B per k-stage

            #pragma unroll
            for (int kk = 0; kk < 4; kk++) {
                int kbB = kk * 32;
                unsigned a[2][4];
                #pragma unroll
                for (int mi = 0; mi < 2; mi++)
                    ldsm4(a[mi][0], a[mi][1], a[mi][2], a[mi][3],
                          aB + mi * 16 * (K1S * 4) + kbB);
                #pragma unroll
                for (int nj2 = 0; nj2 < 2; nj2++) {
                    unsigned pb[4], gb[4];
                    ldsm4(pb[0], pb[1], pb[2], pb[3],
                          pB + nj2 * 16 * (K1_WST * 4) + ksB + kbB);
                    ldsm4(gb[0], gb[1], gb[2], gb[3],
                          gB + nj2 * 16 * (K1_WST * 4) + ksB + kbB);
                    #pragma unroll
                    for (int mi = 0; mi < 2; mi++) {
                        mma_tf32(accP[mi][nj2 * 2 + 0], a[mi], pb + 0);
                        mma_tf32(accG[mi][nj2 * 2 + 0], a[mi], gb + 0);
                        mma_tf32(accP[mi][nj2 * 2 + 1], a[mi], pb + 2);
                        mma_tf32(accG[mi][nj2 * 2 + 1], a[mi], gb + 2);
                    }
                }
            }
            __syncthreads();                // all warps done before A-buf reuse
        }

        // epilogue: h = P * sigmoid(G); per-warp smem transpose (in drained
        // A-buffer region) -> channel-major global stores
        float* Hs = sm1 + w * (32 * 33);
        #pragma unroll
        for (int mi = 0; mi < 2; mi++)
            #pragma unroll
            for (int nj = 0; nj < 4; nj++)
                #pragma unroll
                for (int c = 0; c < 4; c++) {
                    float h = accP[mi][nj][c] / (1.0f + __expf(-accG[mi][nj][c]));
                    int row = mi * 16 + gid + ((c >> 1) << 3);
                    int ch  = nj * 8 + tig * 2 + (c & 1);
                    Hs[ch * 33 + row] = tf32r(h);
                }
        __syncwarp();
        {
            int chG = chTile + wj * 32 + lane;
            float* dst = (chG < HD) ? (g_a + (size_t)chG * NROWS)
                                    : (g_b + (size_t)(chG - HD) * NROWS);
            size_t base = (size_t)rowTile + wi * 32;
            #pragma unroll
            for (int r4 = 0; r4 < 8; r4++) {
                float4 o;
                o.x = Hs[lane * 33 + r4 * 4 + 0];
                o.y = Hs[lane * 33 + r4 * 4 + 1];
                o.z = Hs[lane * 33 + r4 * 4 + 2];
                o.w = Hs[lane * 33 + r4 * 4 + 3];
                *(float4*)(dst + base + r4 * 4) = o;
            }
        }
        __syncthreads();   // Hs reads complete before next rowTile's prologue
    }
}

// ---------------------------------------------------------------------------
// K2 (tf32 MMA + cp.async 2-stage + ldmatrix): R13 version (best measured).
// ---------------------------------------------------------------------------
#define K2S 36
#define K2_BUF (128 * K2S)
#define K2_SMEM_BYTES (4 * K2_BUF * 4)      // 73728

__global__ void __launch_bounds__(256)
k2_einsum() {
    extern __shared__ float sm2[];
    int tid = threadIdx.x;
    int d = blockIdx.z;
    int iTile = blockIdx.x * 128;
    int jTile = blockIdx.y * 128;
    const float* Ab = g_a + (size_t)d * NROWS;
    const float* Bb = g_b + (size_t)d * NROWS;
    int w = tid >> 5, lane = tid & 31;
    int wi = w & 3, wj = w >> 2;
    int gid = lane >> 2, tig = lane & 3;

    int rL = lane & 7;
    int aOff = (rL + ((lane >> 3) & 1) * 8) * (K2S * 4) + (lane >> 4) * 16;
    int bOff = (rL + (lane >> 4) * 8) * (K2S * 4) + ((lane >> 3) & 1) * 16;

    float acc[2][8][4] = {};

    auto load_stage = [&](int s, int buf) {
        int k0 = s * 32;
        float* Ad = sm2 + buf * K2_BUF;
        float* Bd = sm2 + 2 * K2_BUF + buf * K2_BUF;
        #pragma unroll
        for (int rep = 0; rep < 4; rep++) {
            int f = tid + rep * 256;
            int k4 = f & 7, r = f >> 3;
            cpasync16(smem_u32(Ad + r * K2S + k4 * 4),
                      Ab + (size_t)(iTile + r) * NSEQ + k0 + k4 * 4);
            cpasync16(smem_u32(Bd + r * K2S + k4 * 4),
                      Bb + (size_t)(jTile + r) * NSEQ + k0 + k4 * 4);
        }
    };

    load_stage(0, 0);
    CP_COMMIT();

    for (int s = 0; s < 16; s++) {
        int cur = s & 1;
        if (s + 1 < 16) {
            load_stage(s + 1, 1 - cur);
            CP_COMMIT();
            CP_WAIT1();
        } else {
            CP_WAIT0();
        }
        __syncthreads();

        float* As = sm2 + cur * K2_BUF;
        float* Bs = sm2 + 2 * K2_BUF + cur * K2_BUF;
        uint32_t aB = smem_u32(As) + aOff + (wi * 32) * (K2S * 4);
        uint32_t bB = smem_u32(Bs) + bOff + (wj * 64) * (K2S * 4);

        #pragma unroll
        for (int kk = 0; kk < 4; kk++) {
            int kbB = kk * 32;
            unsigned a[2][4];
            #pragma unroll
            for (int mi = 0; mi < 2; mi++)
                ldsm4(a[mi][0], a[mi][1], a[mi][2], a[mi][3],
                      aB + mi * 16 * (K2S * 4) + kbB);
            #pragma unroll
            for (int nj2 = 0; nj2 < 4; nj2++) {
                unsigned bb[4];
                ldsm4(bb[0], bb[1], bb[2], bb[3],
                      bB + nj2 * 16 * (K2S * 4) + kbB);
                #pragma unroll
                for (int mi = 0; mi < 2; mi++) {
                    mma_tf32(acc[mi][nj2 * 2 + 0], a[mi], bb + 0);
                    mma_tf32(acc[mi][nj2 * 2 + 1], a[mi], bb + 2);
                }
            }
        }
        __syncthreads();
    }

    float* T = g_t + (size_t)d * NROWS;
    #pragma unroll
    for (int mi = 0; mi < 2; mi++)
        #pragma unroll
        for (int nj = 0; nj < 8; nj++) {
            int r0 = iTile + wi * 32 + mi * 16 + gid;
            int cj = jTile + wj * 64 + nj * 8 + tig * 2;
            float2 v0 = make_float2(acc[mi][nj][0], acc[mi][nj][1]);
            *(float2*)(T + (size_t)r0 * NSEQ + cj) = v0;
            float2 v1 = make_float2(acc[mi][nj][2], acc[mi][nj][3]);
            *(float2*)(T + (size_t)(r0 + 8) * NSEQ + cj) = v1;
        }
}

// ---------------------------------------------------------------------------
// K3a: tn = LayerNorm_d(t): unchanged (at memory floor).
// ---------------------------------------------------------------------------
__global__ void __launch_bounds__(256)
k3a_ln(const float* __restrict__ nw, const float* __restrict__ nb) {
    __shared__ float Ts[64][132];
    __shared__ float red[4][64], red2[4][64];
    __shared__ float mS[64], rS[64];
    int tid = threadIdx.x;
    int e0 = blockIdx.x * 64;

    #pragma unroll
    for (int rep = 0; rep < 32; rep++) {
        int f = tid + rep * 256;
        int e = f & 63;
        int d = f >> 6;
        Ts[e][d] = g_t[(size_t)d * NROWS + e0 + e];
    }
    __syncthreads();

    {
        int e = tid & 63;
        int dc = tid >> 6;
        float s = 0.f, q = 0.f;
        #pragma unroll
        for (int u4 = 0; u4 < 8; u4++) {
            float4 v = *(const float4*)&Ts[e][dc * 32 + u4 * 4];
            s += v.x + v.y + v.z + v.w;
            q += v.x*v.x + v.y*v.y + v.z*v.z + v.w*v.w;
        }
        red[dc][e] = s;
        red2[dc][e] = q;
    }
    __syncthreads();
    if (tid < 64) {
        float s = red[0][tid] + red[1][tid] + red[2][tid] + red[3][tid];
        float q = red2[0][tid] + red2[1][tid] + red2[2][tid] + red2[3][tid];
        float mean = s * (1.0f / HD);
        float var  = q * (1.0f / HD) - mean * mean;
        mS[tid] = mean;
        rS[tid] = rsqrtf(var + 1e-5f);
    }
    __syncthreads();

    {
        int d4 = tid & 31;
        float4 wv = *(const float4*)(nw + d4 * 4);
        float4 bv = *(const float4*)(nb + d4 * 4);
        #pragma unroll
        for (int rep = 0; rep < 8; rep++) {
            int e = (tid >> 5) + rep * 8;
            float mean = mS[e], rstd = rS[e];
            float4 v = *(const float4*)&Ts[e][d4 * 4];
            float4 o;
            o.x = tf32r((v.x - mean) * rstd * wv.x + bv.x);
            o.y = tf32r((v.y - mean) * rstd * wv.y + bv.y);
            o.z = tf32r((v.z - mean) * rstd * wv.z + bv.z);
            o.w = tf32r((v.w - mean) * rstd * wv.w + bv.w);
            *(float4*)(g_tn + (size_t)(e0 + e) * HD + d4 * 4) = o;
        }
    }
}

// ---------------------------------------------------------------------------
// K3b (tf32 MMA + cp.async + ldmatrix, WEIGHT-RESIDENT): p_out/g_out loaded
// once per CTA (full K, [c][132]); 4 rowTiles per CTA streaming tn/xn tiles.
// ---------------------------------------------------------------------------
#define K3S 20
#define K3_ABUF (128 * K3S)                 // 2560 floats (one matrix stage)
#define K3_ASTAGE (2 * K3_ABUF)             // tn + xn
#define K3_WST 132
#define K3_WSZ (64 * K3_WST)
#define K3_W_OFF (2 * K3_ASTAGE)            // 10240
#define K3_SMEM_BYTES ((2 * K3_ASTAGE + 2 * K3_WSZ) * 4)   // 108544

__global__ void __launch_bounds__(256)
k3b_out(float* __restrict__ out) {
    extern __shared__ float sm3[];
    int tid = threadIdx.x;
    int rowGrp = blockIdx.x;                // 0..511
    int chTile = blockIdx.y * 64;
    const float* powt = g_wr + 65536;
    const float* gowt = g_wr + 81920;
    int w = tid >> 5, lane = tid & 31;
    int wi = w & 3, wj = w >> 2;
    int gid = lane >> 2, tig = lane & 3;

    int rL = lane & 7;
    int aOff  = (rL + ((lane >> 3) & 1) * 8) * (K3S * 4) + (lane >> 4) * 16;
    int bOffW = (rL + (lane >> 4) * 8) * (K3_WST * 4) + ((lane >> 3) & 1) * 16;

    float* Ps = sm3 + K3_W_OFF;
    float* Gs = Ps + K3_WSZ;

    // Load weights once: 64 c x 128 k per matrix
    #pragma unroll
    for (int rep = 0; rep < 8; rep++) {
        int f = tid + rep * 256;            // 0..2047
        int k4 = f & 31, c = f >> 5;
        cpasync16(smem_u32(Ps + c * K3_WST + k4 * 4),
                  powt + (size_t)(chTile + c) * HD + k4 * 4);
        cpasync16(smem_u32(Gs + c * K3_WST + k4 * 4),
                  gowt + (size_t)(chTile + c) * CHN + k4 * 4);
    }

    uint32_t pB = smem_u32(Ps) + bOffW + (wj * 32) * (K3_WST * 4);
    uint32_t gB = smem_u32(Gs) + bOffW + (wj * 32) * (K3_WST * 4);

    auto load_stage = [&](int rowTile, int s, int buf) {
        int k0 = s * 16;
        float* As = sm3 + buf * K3_ASTAGE;
        float* Xs = As + K3_ABUF;
        #pragma unroll
        for (int rep = 0; rep < 2; rep++) {
            int f = tid + rep * 256;        // 0..511
            int k4 = f & 3, r = f >> 2;     // r 0..127
            cpasync16(smem_u32(As + r * K3S + k4 * 4),
                      g_tn + (size_t)(rowTile + r) * HD + k0 + k4 * 4);
            cpasync16(smem_u32(Xs + r * K3S + k4 * 4),
                      g_xn + (size_t)(rowTile + r) * CHN + k0 + k4 * 4);
        }
    };

    for (int rt = 0; rt < 4; rt++) {
        int rowTile = (rowGrp * 4 + rt) * 128;
        float accO[2][4][4] = {}, accG[2][4][4] = {};

        load_stage(rowTile, 0, 0);
        CP_COMMIT();                        // rt==0: group also carries weights

        for (int s = 0; s < 8; s++) {
            int cur = s & 1;
            if (s + 1 < 8) {
                load_stage(rowTile, s + 1, 1 - cur);
                CP_COMMIT();
                CP_WAIT1();
            } else {
                CP_WAIT0();
            }
            __syncthreads();

            float* As = sm3 + cur * K3_ASTAGE;
            float* Xs = As + K3_ABUF;
            uint32_t aB = smem_u32(As) + aOff + (wi * 32) * (K3S * 4);
            uint32_t xB = smem_u32(Xs) + aOff + (wi * 32) * (K3S * 4);
            int ksB = s * 64;               // 16 tf32 * 4B per k-stage

            #pragma unroll
            for (int kk = 0; kk < 2; kk++) {
                int kbB = kk * 32;
                unsigned a[2][4], x[2][4];
                #pragma unroll
                for (int mi = 0; mi < 2; mi++) {
                    ldsm4(a[mi][0], a[mi][1], a[mi][2], a[mi][3],
                          aB + mi * 16 * (K3S * 4) + kbB);
                    ldsm4(x[mi][0], x[mi][1], x[mi][2], x[mi][3],
                          xB + mi * 16 * (K3S * 4) + kbB);
                }
                #pragma unroll
                for (int nj2 = 0; nj2 < 2; nj2++) {
                    unsigned pb[4], gb[4];
                    ldsm4(pb[0], pb[1], pb[2], pb[3],
                          pB + nj2 * 16 * (K3_WST * 4) + ksB + kbB);
                    ldsm4(gb[0], gb[1], gb[2], gb[3],
                          gB + nj2 * 16 * (K3_WST * 4) + ksB + kbB);
                    #pragma unroll
                    for (int mi = 0; mi < 2; mi++) {
                        mma_tf32(accO[mi][nj2 * 2 + 0], a[mi], pb + 0);
                        mma_tf32(accG[mi][nj2 * 2 + 0], x[mi], gb + 0);
                        mma_tf32(accO[mi][nj2 * 2 + 1], a[mi], pb + 2);
                        mma_tf32(accG[mi][nj2 * 2 + 1], x[mi], gb + 2);
                    }
                }
            }
            __syncthreads();                // all warps done before A-buf reuse
        }

        #pragma unroll
        for (int mi = 0; mi < 2; mi++)
            #pragma unroll
            for (int nj = 0; nj < 4; nj++) {
                int r0 = rowTile + wi * 32 + mi * 16 + gid;
                int cj = chTile + wj * 32 + nj * 8 + tig * 2;
                float2 v0;
                v0.x = accO[mi][nj][0] / (1.0f + __expf(-accG[mi][nj][0]));
                v0.y = accO[mi][nj][1] / (1.0f + __expf(-accG[mi][nj][1]));
                *(float2*)(out + (size_t)r0 * CHN + cj) = v0;
                float2 v1;
                v1.x = accO[mi][nj][2] / (1.0f + __expf(-accG[mi][nj][2]));
                v1.y = accO[mi][nj][3] / (1.0f + __expf(-accG[mi][nj][3]));
                *(float2*)(out + (size_t)(r0 + 8) * CHN + cj) = v1;
            }
        __syncthreads();   // stores issued; A bufs safe for next rowTile
    }
}

// ---------------------------------------------------------------------------
extern "C" void kernel_launch(void* const* d_in, const int* in_sizes, int n_in,
                              void* d_out, int out_size) {
    const float* x       = (const float*)d_in[0];
    const float* nin_w   = (const float*)d_in[1];
    const float* nin_b   = (const float*)d_in[2];
    const float* p_in_w  = (const float*)d_in[3];
    const float* g_in_w  = (const float*)d_in[4];
    const float* nout_w  = (const float*)d_in[5];
    const float* nout_b  = (const float*)d_in[6];
    const float* p_out_w = (const float*)d_in[7];
    const float* g_out_w = (const float*)d_in[8];
    float* out = (float*)d_out;

    cudaFuncSetAttribute(k1_proj,
                         cudaFuncAttributeMaxDynamicSharedMemorySize, K1_SMEM_BYTES);
    cudaFuncSetAttribute(k2_einsum,
                         cudaFuncAttributeMaxDynamicSharedMemorySize, K2_SMEM_BYTES);
    cudaFuncSetAttribute(k3b_out,
                         cudaFuncAttributeMaxDynamicSharedMemorySize, K3_SMEM_BYTES);

    kprep    <<<384, 256>>>(p_in_w, g_in_w, p_out_w, g_out_w);
    k0_ln    <<<NROWS / 8, dim3(32, 8)>>>(x, nin_w, nin_b);
    k1_proj  <<<dim3(512, 4), 256, K1_SMEM_BYTES>>>();
    k2_einsum<<<dim3(4, 4, 128), 256, K2_SMEM_BYTES>>>();
    k3a_ln   <<<NROWS / 64, 256>>>(nout_w, nout_b);
    k3b_out  <<<dim3(512, 2), 256, K3_SMEM_BYTES>>>(out);
}

// round 17
// speedup vs baseline: 1.0328x; 1.0020x over previous
#include <cuda_runtime.h>
#include <math.h>
#include <stdint.h>

#define NSEQ 512
#define CHN  128
#define HD   128
#define NROWS (NSEQ*NSEQ)   // 262144

// Scratch (__device__ globals: allocation-free per harness rules)
__device__ float g_xn[(size_t)NROWS * CHN];   // LN(x) row-major [row][c]  (tf32-rounded)
__device__ float g_a [(size_t)HD * NROWS];    // channel-major [d][i*512+k] (tf32-rounded)
__device__ float g_b [(size_t)HD * NROWS];    // channel-major [d][j*512+k] (tf32-rounded)
__device__ float g_t [(size_t)HD * NROWS];    // channel-major [d][i*512+j] (fp32)
__device__ float g_tn[(size_t)NROWS * HD];    // LN_d(t) row-major [e][d]   (tf32-rounded)
__device__ float g_wr[98304];                 // tf32-rounded weights:
                                              // [0,32768) p_in, [32768,65536) g_in,
                                              // [65536,81920) p_out, [81920,98304) g_out

// ---------------------------------------------------------------------------
// helpers
// ---------------------------------------------------------------------------
__device__ __forceinline__ float tf32r(float f) {
    unsigned u;
    asm("cvt.rna.tf32.f32 %0, %1;" : "=r"(u) : "f"(f));
    return __uint_as_float(u);
}

__device__ __forceinline__ void mma_tf32(float* c, const unsigned* a, const unsigned* b) {
    asm volatile(
        "mma.sync.aligned.m16n8k8.row.col.f32.tf32.tf32.f32 "
        "{%0,%1,%2,%3}, {%4,%5,%6,%7}, {%8,%9}, {%0,%1,%2,%3};\n"
        : "+f"(c[0]), "+f"(c[1]), "+f"(c[2]), "+f"(c[3])
        : "r"(a[0]), "r"(a[1]), "r"(a[2]), "r"(a[3]), "r"(b[0]), "r"(b[1]));
}

__device__ __forceinline__ uint32_t smem_u32(const void* p) {
    uint32_t a;
    asm("{ .reg .u64 t; cvta.to.shared.u64 t, %1; cvt.u32.u64 %0, t; }"
        : "=r"(a) : "l"(p));
    return a;
}
__device__ __forceinline__ void cpasync16(uint32_t dst, const void* src) {
    asm volatile("cp.async.cg.shared.global [%0], [%1], 16;" :: "r"(dst), "l"(src));
}
#define CP_COMMIT() asm volatile("cp.async.commit_group;" ::: "memory")
#define CP_WAIT0()  asm volatile("cp.async.wait_group 0;" ::: "memory")
#define CP_WAIT1()  asm volatile("cp.async.wait_group 1;" ::: "memory")

// ldmatrix x4: four 8x8 b16 tiles; for tf32 data each lane receives one 4-byte
// element per tile with mapping (row = lane>>2, tf32col = lane&3).
__device__ __forceinline__ void ldsm4(unsigned& r0, unsigned& r1,
                                      unsigned& r2, unsigned& r3, uint32_t addr) {
    asm volatile("ldmatrix.sync.aligned.m8n8.x4.shared.b16 {%0,%1,%2,%3}, [%4];"
                 : "=r"(r0), "=r"(r1), "=r"(r2), "=r"(r3) : "r"(addr));
}

// ---------------------------------------------------------------------------
// K0: xn = LayerNorm(x) over C=128 (one warp per row, tf32-rounded output).
// Blocks 0..383 additionally tf32-round the weight matrices into g_wr
// (folded former kprep kernel; independent read-only work, same values).
// ---------------------------------------------------------------------------
__global__ void k0_ln(const float* __restrict__ x,
                      const float* __restrict__ w,
                      const float* __restrict__ b,
                      const float* __restrict__ pw, const float* __restrict__ gw,
                      const float* __restrict__ po, const float* __restrict__ go) {
    if (blockIdx.x < 384) {
        int i = blockIdx.x * 256 + threadIdx.y * 32 + threadIdx.x;   // < 98304
        if (i < 32768)        g_wr[i] = tf32r(pw[i]);
        else if (i < 65536)   g_wr[i] = tf32r(gw[i - 32768]);
        else if (i < 81920)   g_wr[i] = tf32r(po[i - 65536]);
        else                  g_wr[i] = tf32r(go[i - 81920]);
    }
    int row  = blockIdx.x * blockDim.y + threadIdx.y;
    int lane = threadIdx.x;
    const float* xr = x + (size_t)row * CHN;
    float4 v = *(const float4*)(xr + lane * 4);
    float s = v.x + v.y + v.z + v.w;
    float q = v.x*v.x + v.y*v.y + v.z*v.z + v.w*v.w;
    #pragma unroll
    for (int o = 16; o > 0; o >>= 1) {
        s += __shfl_xor_sync(0xffffffffu, s, o);
        q += __shfl_xor_sync(0xffffffffu, q, o);
    }
    float mean = s * (1.0f / CHN);
    float var  = q * (1.0f / CHN) - mean * mean;
    float rstd = rsqrtf(var + 1e-5f);
    float4 wv = *(const float4*)(w + lane * 4);
    float4 bv = *(const float4*)(b + lane * 4);
    float4 o;
    o.x = tf32r((v.x - mean) * rstd * wv.x + bv.x);
    o.y = tf32r((v.y - mean) * rstd * wv.y + bv.y);
    o.z = tf32r((v.z - mean) * rstd * wv.z + bv.z);
    o.w = tf32r((v.w - mean) * rstd * wv.w + bv.w);
    *(float4*)(g_xn + (size_t)row * CHN + lane * 4) = o;
}

// ---------------------------------------------------------------------------
// K1 (tf32 MMA + cp.async + ldmatrix, WEIGHT-RESIDENT): unchanged from R16.
// ---------------------------------------------------------------------------
#define K1S 36
#define K1_ABUF (128 * K1S)
#define K1_WST 132
#define K1_WSZ (64 * K1_WST)
#define K1_W_OFF (2 * K1_ABUF)
#define K1_SMEM_BYTES ((2 * K1_ABUF + 2 * K1_WSZ) * 4)   // 104448

__global__ void __launch_bounds__(256)
k1_proj() {
    extern __shared__ float sm1[];
    int tid = threadIdx.x;
    int rowGrp = blockIdx.x;
    int chTile = blockIdx.y * 64;
    const float* wp = g_wr;
    const float* wg = g_wr + 32768;
    int w = tid >> 5, lane = tid & 31;
    int wi = w & 3, wj = w >> 2;
    int gid = lane >> 2, tig = lane & 3;

    int rL = lane & 7;
    int aOff  = (rL + ((lane >> 3) & 1) * 8) * (K1S * 4) + (lane >> 4) * 16;
    int bOffW = (rL + (lane >> 4) * 8) * (K1_WST * 4) + ((lane >> 3) & 1) * 16;

    float* Ps = sm1 + K1_W_OFF;
    float* Gs = Ps + K1_WSZ;

    #pragma unroll
    for (int rep = 0; rep < 8; rep++) {
        int f = tid + rep * 256;
        int k4 = f & 31, c = f >> 5;
        cpasync16(smem_u32(Ps + c * K1_WST + k4 * 4),
                  wp + (size_t)(chTile + c) * CHN + k4 * 4);
        cpasync16(smem_u32(Gs + c * K1_WST + k4 * 4),
                  wg + (size_t)(chTile + c) * CHN + k4 * 4);
    }

    uint32_t pB = smem_u32(Ps) + bOffW + (wj * 32) * (K1_WST * 4);
    uint32_t gB = smem_u32(Gs) + bOffW + (wj * 32) * (K1_WST * 4);

    auto load_stage = [&](int rowTile, int s, int buf) {
        int k0 = s * 32;
        float* As = sm1 + buf * K1_ABUF;
        #pragma unroll
        for (int rep = 0; rep < 4; rep++) {
            int f = tid + rep * 256;
            int k4 = f & 7, r = f >> 3;
            cpasync16(smem_u32(As + r * K1S + k4 * 4),
                      g_xn + (size_t)(rowTile + r) * CHN + k0 + k4 * 4);
        }
    };

    for (int rt = 0; rt < 4; rt++) {
        int rowTile = (rowGrp * 4 + rt) * 128;
        float accP[2][4][4] = {}, accG[2][4][4] = {};

        load_stage(rowTile, 0, 0);
        CP_COMMIT();

        for (int s = 0; s < 4; s++) {
            int cur = s & 1;
            if (s + 1 < 4) {
                load_stage(rowTile, s + 1, 1 - cur);
                CP_COMMIT();
                CP_WAIT1();
            } else {
                CP_WAIT0();
            }
            __syncthreads();

            float* As = sm1 + cur * K1_ABUF;
            uint32_t aB = smem_u32(As) + aOff + (wi * 32) * (K1S * 4);
            int ksB = s * 128;

            #pragma unroll
            for (int kk = 0; kk < 4; kk++) {
                int kbB = kk * 32;
                unsigned a[2][4];
                #pragma unroll
                for (int mi = 0; mi < 2; mi++)
                    ldsm4(a[mi][0], a[mi][1], a[mi][2], a[mi][3],
                          aB + mi * 16 * (K1S * 4) + kbB);
                #pragma unroll
                for (int nj2 = 0; nj2 < 2; nj2++) {
                    unsigned pb[4], gb[4];
                    ldsm4(pb[0], pb[1], pb[2], pb[3],
                          pB + nj2 * 16 * (K1_WST * 4) + ksB + kbB);
                    ldsm4(gb[0], gb[1], gb[2], gb[3],
                          gB + nj2 * 16 * (K1_WST * 4) + ksB + kbB);
                    #pragma unroll
                    for (int mi = 0; mi < 2; mi++) {
                        mma_tf32(accP[mi][nj2 * 2 + 0], a[mi], pb + 0);
                        mma_tf32(accG[mi][nj2 * 2 + 0], a[mi], gb + 0);
                        mma_tf32(accP[mi][nj2 * 2 + 1], a[mi], pb + 2);
                        mma_tf32(accG[mi][nj2 * 2 + 1], a[mi], gb + 2);
                    }
                }
            }
            __syncthreads();
        }

        float* Hs = sm1 + w * (32 * 33);
        #pragma unroll
        for (int mi = 0; mi < 2; mi++)
            #pragma unroll
            for (int nj = 0; nj < 4; nj++)
                #pragma unroll
                for (int c = 0; c < 4; c++) {
                    float h = accP[mi][nj][c] / (1.0f + __expf(-accG[mi][nj][c]));
                    int row = mi * 16 + gid + ((c >> 1) << 3);
                    int ch  = nj * 8 + tig * 2 + (c & 1);
                    Hs[ch * 33 + row] = tf32r(h);
                }
        __syncwarp();
        {
            int chG = chTile + wj * 32 + lane;
            float* dst = (chG < HD) ? (g_a + (size_t)chG * NROWS)
                                    : (g_b + (size_t)(chG - HD) * NROWS);
            size_t base = (size_t)rowTile + wi * 32;
            #pragma unroll
            for (int r4 = 0; r4 < 8; r4++) {
                float4 o;
                o.x = Hs[lane * 33 + r4 * 4 + 0];
                o.y = Hs[lane * 33 + r4 * 4 + 1];
                o.z = Hs[lane * 33 + r4 * 4 + 2];
                o.w = Hs[lane * 33 + r4 * 4 + 3];
                *(float4*)(dst + base + r4 * 4) = o;
            }
        }
        __syncthreads();
    }
}

// ---------------------------------------------------------------------------
// K2 (tf32 MMA + cp.async 2-stage + ldmatrix): unchanged (best measured).
// ---------------------------------------------------------------------------
#define K2S 36
#define K2_BUF (128 * K2S)
#define K2_SMEM_BYTES (4 * K2_BUF * 4)      // 73728

__global__ void __launch_bounds__(256)
k2_einsum() {
    extern __shared__ float sm2[];
    int tid = threadIdx.x;
    int d = blockIdx.z;
    int iTile = blockIdx.x * 128;
    int jTile = blockIdx.y * 128;
    const float* Ab = g_a + (size_t)d * NROWS;
    const float* Bb = g_b + (size_t)d * NROWS;
    int w = tid >> 5, lane = tid & 31;
    int wi = w & 3, wj = w >> 2;
    int gid = lane >> 2, tig = lane & 3;

    int rL = lane & 7;
    int aOff = (rL + ((lane >> 3) & 1) * 8) * (K2S * 4) + (lane >> 4) * 16;
    int bOff = (rL + (lane >> 4) * 8) * (K2S * 4) + ((lane >> 3) & 1) * 16;

    float acc[2][8][4] = {};

    auto load_stage = [&](int s, int buf) {
        int k0 = s * 32;
        float* Ad = sm2 + buf * K2_BUF;
        float* Bd = sm2 + 2 * K2_BUF + buf * K2_BUF;
        #pragma unroll
        for (int rep = 0; rep < 4; rep++) {
            int f = tid + rep * 256;
            int k4 = f & 7, r = f >> 3;
            cpasync16(smem_u32(Ad + r * K2S + k4 * 4),
                      Ab + (size_t)(iTile + r) * NSEQ + k0 + k4 * 4);
            cpasync16(smem_u32(Bd + r * K2S + k4 * 4),
                      Bb + (size_t)(jTile + r) * NSEQ + k0 + k4 * 4);
        }
    };

    load_stage(0, 0);
    CP_COMMIT();

    for (int s = 0; s < 16; s++) {
        int cur = s & 1;
        if (s + 1 < 16) {
            load_stage(s + 1, 1 - cur);
            CP_COMMIT();
            CP_WAIT1();
        } else {
            CP_WAIT0();
        }
        __syncthreads();

        float* As = sm2 + cur * K2_BUF;
        float* Bs = sm2 + 2 * K2_BUF + cur * K2_BUF;
        uint32_t aB = smem_u32(As) + aOff + (wi * 32) * (K2S * 4);
        uint32_t bB = smem_u32(Bs) + bOff + (wj * 64) * (K2S * 4);

        #pragma unroll
        for (int kk = 0; kk < 4; kk++) {
            int kbB = kk * 32;
            unsigned a[2][4];
            #pragma unroll
            for (int mi = 0; mi < 2; mi++)
                ldsm4(a[mi][0], a[mi][1], a[mi][2], a[mi][3],
                      aB + mi * 16 * (K2S * 4) + kbB);
            #pragma unroll
            for (int nj2 = 0; nj2 < 4; nj2++) {
                unsigned bb[4];
                ldsm4(bb[0], bb[1], bb[2], bb[3],
                      bB + nj2 * 16 * (K2S * 4) + kbB);
                #pragma unroll
                for (int mi = 0; mi < 2; mi++) {
                    mma_tf32(acc[mi][nj2 * 2 + 0], a[mi], bb + 0);
                    mma_tf32(acc[mi][nj2 * 2 + 1], a[mi], bb + 2);
                }
            }
        }
        __syncthreads();
    }

    float* T = g_t + (size_t)d * NROWS;
    #pragma unroll
    for (int mi = 0; mi < 2; mi++)
        #pragma unroll
        for (int nj = 0; nj < 8; nj++) {
            int r0 = iTile + wi * 32 + mi * 16 + gid;
            int cj = jTile + wj * 64 + nj * 8 + tig * 2;
            float2 v0 = make_float2(acc[mi][nj][0], acc[mi][nj][1]);
            *(float2*)(T + (size_t)r0 * NSEQ + cj) = v0;
            float2 v1 = make_float2(acc[mi][nj][2], acc[mi][nj][3]);
            *(float2*)(T + (size_t)(r0 + 8) * NSEQ + cj) = v1;
        }
}

// ---------------------------------------------------------------------------
// K3a: tn = LayerNorm_d(t) transpose. WIDENED: 128 e per CTA, 512 threads,
// dynamic smem. Reduction tree per element is IDENTICAL to the previous
// version (same 32-d chunks, same 4-way final sum) -> bit-identical output.
// ---------------------------------------------------------------------------
#define K3A_SMEM_BYTES ((128 * 132 + 8 * 128 + 2 * 128) * 4)   // 72704

__global__ void __launch_bounds__(512)
k3a_ln(const float* __restrict__ nw, const float* __restrict__ nb) {
    extern __shared__ float sma[];
    float* Ts   = sma;                       // [128][132]
    float* red  = Ts + 128 * 132;            // [4][128]
    float* red2 = red + 4 * 128;             // [4][128]
    float* mS   = red2 + 4 * 128;            // [128]
    float* rS   = mS + 128;                  // [128]
    int tid = threadIdx.x;
    int e0 = blockIdx.x * 128;

    // load transposed: per d, 512B contiguous (128 e)
    #pragma unroll
    for (int rep = 0; rep < 32; rep++) {
        int f = tid + rep * 512;             // 0..16383
        int e = f & 127;
        int d = f >> 7;                      // 0..127
        Ts[e * 132 + d] = g_t[(size_t)d * NROWS + e0 + e];
    }
    __syncthreads();

    // stats: thread (e = tid&127, dc = tid>>7) reduces its 32-d chunk,
    // same chunking/order as the 64-e version.
    {
        int e = tid & 127;
        int dc = tid >> 7;                   // 0..3
        float s = 0.f, q = 0.f;
        #pragma unroll
        for (int u4 = 0; u4 < 8; u4++) {
            float4 v = *(const float4*)&Ts[e * 132 + dc * 32 + u4 * 4];
            s += v.x + v.y + v.z + v.w;
            q += v.x*v.x + v.y*v.y + v.z*v.z + v.w*v.w;
        }
        red [dc * 128 + e] = s;
        red2[dc * 128 + e] = q;
    }
    __syncthreads();
    if (tid < 128) {
        float s = red[0 * 128 + tid] + red[1 * 128 + tid]
                + red[2 * 128 + tid] + red[3 * 128 + tid];
        float q = red2[0 * 128 + tid] + red2[1 * 128 + tid]
                + red2[2 * 128 + tid] + red2[3 * 128 + tid];
        float mean = s * (1.0f / HD);
        float var  = q * (1.0f / HD) - mean * mean;
        mS[tid] = mean;
        rS[tid] = rsqrtf(var + 1e-5f);
    }
    __syncthreads();

    // normalize + write row-major, coalesced over d
    {
        int d4 = tid & 31;
        float4 wv = *(const float4*)(nw + d4 * 4);
        float4 bv = *(const float4*)(nb + d4 * 4);
        #pragma unroll
        for (int rep = 0; rep < 8; rep++) {
            int e = (tid >> 5) + rep * 16;   // 0..127
            float mean = mS[e], rstd = rS[e];
            float4 v = *(const float4*)&Ts[e * 132 + d4 * 4];
            float4 o;
            o.x = tf32r((v.x - mean) * rstd * wv.x + bv.x);
            o.y = tf32r((v.y - mean) * rstd * wv.y + bv.y);
            o.z = tf32r((v.z - mean) * rstd * wv.z + bv.z);
            o.w = tf32r((v.w - mean) * rstd * wv.w + bv.w);
            *(float4*)(g_tn + (size_t)(e0 + e) * HD + d4 * 4) = o;
        }
    }
}

// ---------------------------------------------------------------------------
// K3b (tf32 MMA + cp.async + ldmatrix, WEIGHT-RESIDENT): unchanged from R16.
// ---------------------------------------------------------------------------
#define K3S 20
#define K3_ABUF (128 * K3S)
#define K3_ASTAGE (2 * K3_ABUF)
#define K3_WST 132
#define K3_WSZ (64 * K3_WST)
#define K3_W_OFF (2 * K3_ASTAGE)
#define K3_SMEM_BYTES ((2 * K3_ASTAGE + 2 * K3_WSZ) * 4)   // 108544

__global__ void __launch_bounds__(256)
k3b_out(float* __restrict__ out) {
    extern __shared__ float sm3[];
    int tid = threadIdx.x;
    int rowGrp = blockIdx.x;
    int chTile = blockIdx.y * 64;
    const float* powt = g_wr + 65536;
    const float* gowt = g_wr + 81920;
    int w = tid >> 5, lane = tid & 31;
    int wi = w & 3, wj = w >> 2;
    int gid = lane >> 2, tig = lane & 3;

    int rL = lane & 7;
    int aOff  = (rL + ((lane >> 3) & 1) * 8) * (K3S * 4) + (lane >> 4) * 16;
    int bOffW = (rL + (lane >> 4) * 8) * (K3_WST * 4) + ((lane >> 3) & 1) * 16;

    float* Ps = sm3 + K3_W_OFF;
    float* Gs = Ps + K3_WSZ;

    #pragma unroll
    for (int rep = 0; rep < 8; rep++) {
        int f = tid + rep * 256;
        int k4 = f & 31, c = f >> 5;
        cpasync16(smem_u32(Ps + c * K3_WST + k4 * 4),
                  powt + (size_t)(chTile + c) * HD + k4 * 4);
        cpasync16(smem_u32(Gs + c * K3_WST + k4 * 4),
                  gowt + (size_t)(chTile + c) * CHN + k4 * 4);
    }

    uint32_t pB = smem_u32(Ps) + bOffW + (wj * 32) * (K3_WST * 4);
    uint32_t gB = smem_u32(Gs) + bOffW + (wj * 32) * (K3_WST * 4);

    auto load_stage = [&](int rowTile, int s, int buf) {
        int k0 = s * 16;
        float* As = sm3 + buf * K3_ASTAGE;
        float* Xs = As + K3_ABUF;
        #pragma unroll
        for (int rep = 0; rep < 2; rep++) {
            int f = tid + rep * 256;
            int k4 = f & 3, r = f >> 2;
            cpasync16(smem_u32(As + r * K3S + k4 * 4),
                      g_tn + (size_t)(rowTile + r) * HD + k0 + k4 * 4);
            cpasync16(smem_u32(Xs + r * K3S + k4 * 4),
                      g_xn + (size_t)(rowTile + r) * CHN + k0 + k4 * 4);
        }
    };

    for (int rt = 0; rt < 4; rt++) {
        int rowTile = (rowGrp * 4 + rt) * 128;
        float accO[2][4][4] = {}, accG[2][4][4] = {};

        load_stage(rowTile, 0, 0);
        CP_COMMIT();

        for (int s = 0; s < 8; s++) {
            int cur = s & 1;
            if (s + 1 < 8) {
                load_stage(rowTile, s + 1, 1 - cur);
                CP_COMMIT();
                CP_WAIT1();
            } else {
                CP_WAIT0();
            }
            __syncthreads();

            float* As = sm3 + cur * K3_ASTAGE;
            float* Xs = As + K3_ABUF;
            uint32_t aB = smem_u32(As) + aOff + (wi * 32) * (K3S * 4);
            uint32_t xB = smem_u32(Xs) + aOff + (wi * 32) * (K3S * 4);
            int ksB = s * 64;

            #pragma unroll
            for (int kk = 0; kk < 2; kk++) {
                int kbB = kk * 32;
                unsigned a[2][4], x[2][4];
                #pragma unroll
                for (int mi = 0; mi < 2; mi++) {
                    ldsm4(a[mi][0], a[mi][1], a[mi][2], a[mi][3],
                          aB + mi * 16 * (K3S * 4) + kbB);
                    ldsm4(x[mi][0], x[mi][1], x[mi][2], x[mi][3],
                          xB + mi * 16 * (K3S * 4) + kbB);
                }
                #pragma unroll
                for (int nj2 = 0; nj2 < 2; nj2++) {
                    unsigned pb[4], gb[4];
                    ldsm4(pb[0], pb[1], pb[2], pb[3],
                          pB + nj2 * 16 * (K3_WST * 4) + ksB + kbB);
                    ldsm4(gb[0], gb[1], gb[2], gb[3],
                          gB + nj2 * 16 * (K3_WST * 4) + ksB + kbB);
                    #pragma unroll
                    for (int mi = 0; mi < 2; mi++) {
                        mma_tf32(accO[mi][nj2 * 2 + 0], a[mi], pb + 0);
                        mma_tf32(accG[mi][nj2 * 2 + 0], x[mi], gb + 0);
                        mma_tf32(accO[mi][nj2 * 2 + 1], a[mi], pb + 2);
                        mma_tf32(accG[mi][nj2 * 2 + 1], x[mi], gb + 2);
                    }
                }
            }
            __syncthreads();
        }

        #pragma unroll
        for (int mi = 0; mi < 2; mi++)
            #pragma unroll
            for (int nj = 0; nj < 4; nj++) {
                int r0 = rowTile + wi * 32 + mi * 16 + gid;
                int cj = chTile + wj * 32 + nj * 8 + tig * 2;
                float2 v0;
                v0.x = accO[mi][nj][0] / (1.0f + __expf(-accG[mi][nj][0]));
                v0.y = accO[mi][nj][1] / (1.0f + __expf(-accG[mi][nj][1]));
                *(float2*)(out + (size_t)r0 * CHN + cj) = v0;
                float2 v1;
                v1.x = accO[mi][nj][2] / (1.0f + __expf(-accG[mi][nj][2]));
                v1.y = accO[mi][nj][3] / (1.0f + __expf(-accG[mi][nj][3]));
                *(float2*)(out + (size_t)(r0 + 8) * CHN + cj) = v1;
            }
        __syncthreads();
    }
}

// ---------------------------------------------------------------------------
extern "C" void kernel_launch(void* const* d_in, const int* in_sizes, int n_in,
                              void* d_out, int out_size) {
    const float* x       = (const float*)d_in[0];
    const float* nin_w   = (const float*)d_in[1];
    const float* nin_b   = (const float*)d_in[2];
    const float* p_in_w  = (const float*)d_in[3];
    const float* g_in_w  = (const float*)d_in[4];
    const float* nout_w  = (const float*)d_in[5];
    const float* nout_b  = (const float*)d_in[6];
    const float* p_out_w = (const float*)d_in[7];
    const float* g_out_w = (const float*)d_in[8];
    float* out = (float*)d_out;

    cudaFuncSetAttribute(k1_proj,
                         cudaFuncAttributeMaxDynamicSharedMemorySize, K1_SMEM_BYTES);
    cudaFuncSetAttribute(k2_einsum,
                         cudaFuncAttributeMaxDynamicSharedMemorySize, K2_SMEM_BYTES);
    cudaFuncSetAttribute(k3a_ln,
                         cudaFuncAttributeMaxDynamicSharedMemorySize, K3A_SMEM_BYTES);
    cudaFuncSetAttribute(k3b_out,
                         cudaFuncAttributeMaxDynamicSharedMemorySize, K3_SMEM_BYTES);

    k0_ln    <<<NROWS / 8, dim3(32, 8)>>>(x, nin_w, nin_b,
                                          p_in_w, g_in_w, p_out_w, g_out_w);
    k1_proj  <<<dim3(512, 4), 256, K1_SMEM_BYTES>>>();
    k2_einsum<<<dim3(4, 4, 128), 256, K2_SMEM_BYTES>>>();
    k3a_ln   <<<NROWS / 128, 512, K3A_SMEM_BYTES>>>(nout_w, nout_b);
    k3b_out  <<<dim3(512, 2), 256, K3_SMEM_BYTES>>>(out);
}